// round 14
// baseline (speedup 1.0000x reference)
#include <cuda_runtime.h>
#include <cuda_fp16.h>
#include <math.h>
#include <stdint.h>

#define B_   32
#define G_   15
#define K_   2048
#define NG   480
#define NG2  960
#define NPTS 983040
#define TILE_P 128
#define ZSTR 36
#define OUT_LF_OFF 8192
#define NB   128            // persistent tail grid

__constant__ int c_split[15] = {0,1,8, 2,4,6, 3,5,7, 9,11,13, 10,12,14};

// ---------------- device scratch ----------------
__device__ float  g_cent[NG*3];
__device__ float  g_S0p[NG*6];
__device__ float4 g_w0s[64];
__device__ float  g_max1[64*NG2];
__device__ float  g_min1[64*NG2];
__device__ float  g_psum1[64*NG2];
__device__ float  g_psq1[64*NG2];
__device__ float  g_sc1[64];
__device__ float  g_bi1[64];
__device__ float  g_lf1[NG*64];
__device__ float  g_yB[480*128];
__device__ float  g_scaleA[128];
__device__ float  g_biasA[128];
__device__ float  g_s3in[160*131];
__device__ float  g_yD[160*256];
__device__ float  g_scaleC[256];
__device__ float  g_biasC[256];
__device__ float  g_WAT[67*128];
__device__ float  g_WBT[128*128];
__device__ float  g_WCT[131*256];
__device__ float  g_WDT[256*256];
__device__ volatile unsigned g_bar;

__device__ __forceinline__ uint32_t h2u(__half2 h) { uint32_t u; memcpy(&u, &h, 4); return u; }
__device__ __forceinline__ uint32_t smem_u32(const void* p) {
    uint32_t a;
    asm("{ .reg .u64 tmp; cvta.to.shared.u64 tmp, %1; cvt.u32.u64 %0, tmp; }" : "=r"(a) : "l"(p));
    return a;
}

#define MMA_F16(d, a, b)                                                      \
    asm volatile(                                                             \
        "mma.sync.aligned.m16n8k16.row.col.f32.f16.f16.f32 "                  \
        "{%0,%1,%2,%3}, {%4,%5,%6,%7}, {%8,%9}, {%0,%1,%2,%3};"               \
        : "+f"((d)[0]), "+f"((d)[1]), "+f"((d)[2]), "+f"((d)[3])              \
        : "r"((a)[0]), "r"((a)[1]), "r"((a)[2]), "r"((a)[3]),                 \
          "r"((b)[0]), "r"((b)[1]))

#define LDM_X4(r, addr)                                                       \
    asm volatile("ldmatrix.sync.aligned.m8n8.x4.shared.b16 {%0,%1,%2,%3}, [%4];" \
        : "=r"((r)[0]), "=r"((r)[1]), "=r"((r)[2]), "=r"((r)[3]) : "r"(addr))

// ---------------- stage 1: centroids + 3x3 second-moment partials ----------------
__global__ void k_centroid(const float* __restrict__ x, float* __restrict__ out) {
    __shared__ float red[9*256];
    int blk = blockIdx.x, t = threadIdx.x;
    const float4* xg4 = (const float4*)(x + (size_t)blk * (K_*3));
    float s0=0,s1=0,s2=0,m00=0,m01=0,m02=0,m11=0,m12=0,m22=0;
    #pragma unroll
    for (int it = 0; it < 2; it++) {
        int cidx = t + it*256;
        const float4* cp = xg4 + cidx*3;
        float4 A = cp[0], Bv = cp[1], C = cp[2];
        float px[4] = {A.x, A.w, Bv.z, C.y};
        float py[4] = {A.y, Bv.x, Bv.w, C.z};
        float pz[4] = {A.z, Bv.y, C.x, C.w};
        #pragma unroll
        for (int j = 0; j < 4; j++) {
            float a = px[j], b = py[j], c = pz[j];
            s0+=a; s1+=b; s2+=c;
            m00=fmaf(a,a,m00); m01=fmaf(a,b,m01); m02=fmaf(a,c,m02);
            m11=fmaf(b,b,m11); m12=fmaf(b,c,m12); m22=fmaf(c,c,m22);
        }
    }
    red[0*256+t]=s0; red[1*256+t]=s1; red[2*256+t]=s2;
    red[3*256+t]=m00; red[4*256+t]=m01; red[5*256+t]=m02;
    red[6*256+t]=m11; red[7*256+t]=m12; red[8*256+t]=m22;
    __syncthreads();
    for (int s = 128; s > 0; s >>= 1) {
        if (t < s) {
            #pragma unroll
            for (int j = 0; j < 9; j++) red[j*256+t] += red[j*256+t+s];
        }
        __syncthreads();
    }
    if (t == 0) {
        const float invK = 1.0f / (float)K_;
        float C0 = red[0]*invK, C1 = red[256]*invK, C2 = red[512]*invK;
        g_cent[blk*3+0]=C0; g_cent[blk*3+1]=C1; g_cent[blk*3+2]=C2;
        g_S0p[blk*6+0] = red[3*256] - (float)K_*C0*C0;
        g_S0p[blk*6+1] = red[4*256] - (float)K_*C0*C1;
        g_S0p[blk*6+2] = red[5*256] - (float)K_*C0*C2;
        g_S0p[blk*6+3] = red[6*256] - (float)K_*C1*C1;
        g_S0p[blk*6+4] = red[7*256] - (float)K_*C1*C2;
        g_S0p[blk*6+5] = red[8*256] - (float)K_*C2*C2;
        int b = blk / G_, g = blk % G_;
        out[OUT_LF_OFF + (b*67+0)*15 + g] = C0;
        out[OUT_LF_OFF + (b*67+1)*15 + g] = C1;
        out[OUT_LF_OFF + (b*67+2)*15 + g] = C2;
    }
}

// layer-0 BN fold + rel3 channels of s3in + tail-barrier reset
__global__ void k_bn0(const float* __restrict__ W0, const float* __restrict__ g0,
                      const float* __restrict__ b0) {
    __shared__ float S[6];
    int t = threadIdx.x, w = t >> 5, lane = t & 31;
    if (t == 0) g_bar = 0;
    if (w < 6) {
        float s = 0.f;
        for (int p = lane; p < NG; p += 32) s += g_S0p[p*6 + w];
        #pragma unroll
        for (int o = 16; o > 0; o >>= 1) s += __shfl_down_sync(0xffffffffu, s, o);
        if (lane == 0) S[w] = s;
    }
    if (t < 160) {
        int bb = t / 5, sIdx = t % 5;
        float c2s[3] = {0,0,0}, c3[3] = {0,0,0};
        #pragma unroll
        for (int ss = 0; ss < 5; ss++) {
            int ga = c_split[ss*3+0], gb1 = c_split[ss*3+1], gc = c_split[ss*3+2];
            #pragma unroll
            for (int i = 0; i < 3; i++) {
                float v = (g_cent[(bb*15+ga)*3+i] + g_cent[(bb*15+gb1)*3+i]
                         + g_cent[(bb*15+gc)*3+i]) * (1.f/3.f);
                c3[i] += v;
                if (ss == sIdx) c2s[i] = v;
            }
        }
        #pragma unroll
        for (int i = 0; i < 3; i++)
            g_s3in[t*131 + i] = c2s[i] - c3[i]*0.2f;
    }
    __syncthreads();
    if (t < 64) {
        float w0 = W0[t*3+0], w1 = W0[t*3+1], w2 = W0[t*3+2];
        float var = (w0*w0*S[0] + w1*w1*S[3] + w2*w2*S[5]
                   + 2.f*(w0*w1*S[1] + w0*w2*S[2] + w1*w2*S[4])) * (1.0f/(float)NPTS);
        float scl = g0[t] * rsqrtf(var + 1e-5f);
        g_w0s[t] = make_float4(scl*w0, scl*w1, scl*w2, b0[t]);
    }
}

// ---------------- stage 1 main pass: hi-only HMMA via ldmatrix + exact argmax refine ----------------
__global__ void __launch_bounds__(256,2) k_main(const float* __restrict__ x,
                                                const float* __restrict__ W1) {
    extern __shared__ float smem[];
    uint32_t* sWhi = (uint32_t*)smem;
    uint32_t* sZ   = sWhi + 2048;
    float*    sRedV = (float*)sZ;
    int*      sRedI = (int*)(sZ + 2048);
    int*      sBI   = (int*)(sZ + 4096);
    float4*   sW0s  = (float4*)(sZ + 4608);
    float*    sCen  = (float*)(sW0s + 64);

    const int blk = blockIdx.x, t = threadIdx.x;
    const int grp = blk >> 1, half = blk & 1;
    const int lane = t & 31, w = t >> 5;
    const int wm = w >> 1, wn = w & 1;
    const int gid = lane >> 2, tig = lane & 3;

    for (int idx = t; idx < 2048; idx += 256) {
        int n = idx >> 5, kk = idx & 31;
        sWhi[idx] = h2u(__floats2half2_rn(W1[n*64 + 2*kk], W1[n*64 + 2*kk + 1]));
    }
    if (t < 64) sW0s[t] = g_w0s[t];
    if (t < 3)  sCen[t] = g_cent[grp*3 + t];
    __syncthreads();

    uint32_t bh[4][4][2];
    {
        const int n0 = wn * 32;
        #pragma unroll
        for (int nt = 0; nt < 4; nt++)
            #pragma unroll
            for (int k0 = 0; k0 < 4; k0++) {
                const int base = (n0 + nt*8 + gid)*32 + k0*8 + tig;
                bh[nt][k0][0] = sWhi[base];
                bh[nt][k0][1] = sWhi[base + 4];
            }
    }

    const float* xg = x + ((size_t)grp * K_ + half * 1024) * 3;
    const float c0 = sCen[0], c1 = sCen[1], c2v = sCen[2];
    const int h  = w >> 2;
    const int p1 = (w & 3) * 32 + lane;

    // ldmatrix per-lane address components
    const int lrow = (lane & 7) + ((lane & 8) ? 8 : 0);
    const int lcol = (lane & 16) ? 4 : 0;
    const uint32_t zbase = smem_u32(sZ);
    const int ptb = wm * 32;
    const uint32_t a_addr0 = zbase + (uint32_t)(((ptb + lrow)*ZSTR + lcol) * 4);
    const uint32_t a_addr1 = a_addr0 + 16*ZSTR*4;

    float mx[8], mn[8], sm[8], sq[8];
    int   xini[8];
    #pragma unroll
    for (int s = 0; s < 8; s++) {
        mx[s]=-3.402823e38f; mn[s]=3.402823e38f; sm[s]=0.f; sq[s]=0.f; xini[s]=0;
    }

    for (int tile = 0; tile < 8; tile++) {
        {
            const float* xp = xg + (size_t)(tile*128 + p1)*3;
            float r0 = xp[0]-c0, r1 = xp[1]-c1, r2 = xp[2]-c2v;
            uint32_t zh2[16];
            #pragma unroll
            for (int j = 0; j < 16; j++) {
                float4 qa = sW0s[h*32 + 2*j];
                float4 qb = sW0s[h*32 + 2*j + 1];
                float za = fmaxf(fmaf(qa.x, r0, fmaf(qa.y, r1, fmaf(qa.z, r2, qa.w))), 0.f);
                float zb = fmaxf(fmaf(qb.x, r0, fmaf(qb.y, r1, fmaf(qb.z, r2, qb.w))), 0.f);
                zh2[j] = h2u(__floats2half2_rn(za, zb));
            }
            uint4* zh = (uint4*)(sZ + p1*ZSTR + h*16);
            #pragma unroll
            for (int j4 = 0; j4 < 4; j4++)
                zh[j4] = make_uint4(zh2[j4*4], zh2[j4*4+1], zh2[j4*4+2], zh2[j4*4+3]);
        }
        __syncthreads();

        float acc[2][4][4];
        #pragma unroll
        for (int m = 0; m < 2; m++)
            #pragma unroll
            for (int nt = 0; nt < 4; nt++)
                #pragma unroll
                for (int r = 0; r < 4; r++) acc[m][nt][r] = 0.f;

        #pragma unroll
        for (int k0 = 0; k0 < 4; k0++) {
            uint32_t ah[2][4];
            LDM_X4(ah[0], a_addr0 + k0*32);
            LDM_X4(ah[1], a_addr1 + k0*32);
            #pragma unroll
            for (int m = 0; m < 2; m++)
                #pragma unroll
                for (int nt = 0; nt < 4; nt++)
                    MMA_F16(acc[m][nt], ah[m], bh[nt][k0]);
        }

        #pragma unroll
        for (int m = 0; m < 2; m++)
            #pragma unroll
            for (int nt = 0; nt < 4; nt++)
                #pragma unroll
                for (int r = 0; r < 4; r++) {
                    float v = acc[m][nt][r];
                    int s = nt*2 + (r & 1);
                    int pidx = tile*128 + wm*32 + m*16 + gid + (r>>1)*8;
                    if (v > mx[s]) { mx[s] = v; xini[s] = (xini[s] & 0xFFFF0000) | pidx; }
                    if (v < mn[s]) { mn[s] = v; xini[s] = (xini[s] & 0x0000FFFF) | (pidx << 16); }
                    sm[s] += v;
                    sq[s] = fmaf(v, v, sq[s]);
                }
        __syncthreads();
    }

    const int slot = wm*8 + gid;
    #pragma unroll
    for (int s = 0; s < 8; s++) {
        int ch = wn*32 + (s>>1)*8 + 2*tig + (s&1);
        sRedV[ch*32 + slot] = mx[s];
        sRedI[ch*32 + slot] = xini[s] & 0xFFFF;
    }
    __syncthreads();
    if (t < 64) {
        float v = sRedV[t*32]; int bi = sRedI[t*32];
        #pragma unroll
        for (int j = 1; j < 32; j++) {
            float u = sRedV[t*32+j];
            if (u > v) { v = u; bi = sRedI[t*32+j]; }
        }
        sBI[t] = bi;
    }
    __syncthreads();
    #pragma unroll
    for (int s = 0; s < 8; s++) {
        int ch = wn*32 + (s>>1)*8 + 2*tig + (s&1);
        sRedV[ch*32 + slot] = mn[s];
        sRedI[ch*32 + slot] = (xini[s] >> 16) & 0xFFFF;
    }
    __syncthreads();
    if (t < 64) {
        float v = sRedV[t*32]; int bi = sRedI[t*32];
        #pragma unroll
        for (int j = 1; j < 32; j++) {
            float u = sRedV[t*32+j];
            if (u < v) { v = u; bi = sRedI[t*32+j]; }
        }
        sBI[64 + t] = bi;
    }
    __syncthreads();
    #pragma unroll
    for (int s = 0; s < 8; s++)
        sRedV[(wn*32 + (s>>1)*8 + 2*tig + (s&1))*32 + slot] = sm[s];
    __syncthreads();
    if (t < 64) {
        float v = 0.f;
        #pragma unroll
        for (int j = 0; j < 32; j++) v += sRedV[t*32+j];
        g_psum1[t*NG2 + blk] = v;
    }
    __syncthreads();
    #pragma unroll
    for (int s = 0; s < 8; s++)
        sRedV[(wn*32 + (s>>1)*8 + 2*tig + (s&1))*32 + slot] = sq[s];
    __syncthreads();
    if (t < 64) {
        float v = 0.f;
        #pragma unroll
        for (int j = 0; j < 32; j++) v += sRedV[t*32+j];
        g_psq1[t*NG2 + blk] = v;
    }

    if (t < 128) {
        int c = t & 63;
        int p = sBI[t];
        const float* xp = xg + (size_t)p*3;
        float r0 = xp[0]-c0, r1 = xp[1]-c1, r2 = xp[2]-c2v;
        const float4* w4 = (const float4*)(W1 + c*64);
        float y = 0.f;
        #pragma unroll 4
        for (int j = 0; j < 16; j++) {
            float4 wv = w4[j];
            float4 q0 = sW0s[4*j+0], q1 = sW0s[4*j+1], q2 = sW0s[4*j+2], q3 = sW0s[4*j+3];
            float z0 = fmaxf(fmaf(q0.x, r0, fmaf(q0.y, r1, fmaf(q0.z, r2, q0.w))), 0.f);
            float z1 = fmaxf(fmaf(q1.x, r0, fmaf(q1.y, r1, fmaf(q1.z, r2, q1.w))), 0.f);
            float z2 = fmaxf(fmaf(q2.x, r0, fmaf(q2.y, r1, fmaf(q2.z, r2, q2.w))), 0.f);
            float z3 = fmaxf(fmaf(q3.x, r0, fmaf(q3.y, r1, fmaf(q3.z, r2, q3.w))), 0.f);
            y = fmaf(wv.x, z0, y); y = fmaf(wv.y, z1, y);
            y = fmaf(wv.z, z2, y); y = fmaf(wv.w, z3, y);
        }
        if (t < 64) g_max1[c*NG2 + blk] = y;
        else        g_min1[c*NG2 + blk] = y;
    }
}

// ---------------- persistent tail: 8 phases, 7 barriers, 128 all-resident blocks ----------------
__device__ __forceinline__ void gbar(int phase) {
    __syncthreads();
    if (threadIdx.x == 0) {
        __threadfence();
        atomicAdd((unsigned*)&g_bar, 1u);
        unsigned tgt = (unsigned)NB * (unsigned)(phase + 1);
        while (g_bar < tgt) { }
        __threadfence();
    }
    __syncthreads();
}

__global__ void __launch_bounds__(256) k_tail(
    const float* __restrict__ g1, const float* __restrict__ b1,
    const float* __restrict__ WA, const float* __restrict__ gA, const float* __restrict__ bA,
    const float* __restrict__ WB, const float* __restrict__ gB, const float* __restrict__ bB,
    const float* __restrict__ WC, const float* __restrict__ gC, const float* __restrict__ bC,
    const float* __restrict__ WD, const float* __restrict__ gD, const float* __restrict__ bD,
    float* __restrict__ out)
{
    __shared__ float rs[256], rq[256];
    __shared__ float sw[136];
    __shared__ float fA[2][68], zA[2][128];
    __shared__ float fC[132], zC[256];
    __shared__ float ps[8], pq[8], sbx[2];
    const int bid = blockIdx.x, t = threadIdx.x;
    const int wp = t >> 5, l = t & 31;

    // P0: blocks 0-63: layer-1 BN stats; blocks 64-127: weight transposes
    if (bid < 64) {
        int c = bid;
        float s = 0.f, q = 0.f;
        for (int p = t; p < NG2; p += 256) { s += g_psum1[c*NG2+p]; q += g_psq1[c*NG2+p]; }
        rs[t] = s; rq[t] = q;
        __syncthreads();
        for (int o = 128; o > 0; o >>= 1) {
            if (t < o) { rs[t] += rs[t+o]; rq[t] += rq[t+o]; }
            __syncthreads();
        }
        if (t == 0) {
            float mean = rs[0] * (1.0f/(float)NPTS);
            float var  = rq[0] * (1.0f/(float)NPTS) - mean*mean;
            float scl  = g1[c] * rsqrtf(var + 1e-5f);
            g_sc1[c] = scl;
            g_bi1[c] = b1[c] - mean*scl;
        }
    } else {
        int base = (bid - 64)*256 + t;
        const int stride = 64*256;
        for (int i = base; i < 67*128; i += stride) { int k = i>>7, c = i&127; g_WAT[i] = WA[c*67+k]; }
        for (int i = base; i < 128*128; i += stride) { int k = i>>7, c = i&127; g_WBT[i] = WB[c*128+k]; }
        for (int i = base; i < 131*256; i += stride) { int k = i>>8, c = i&255; g_WCT[i] = WC[c*131+k]; }
        for (int i = base; i < 256*256; i += stride) { int k = i>>8, c = i&255; g_WDT[i] = WD[c*256+k]; }
    }
    gbar(0);

    // P1: lf1 + local_features output
    for (int idx = bid*256 + t; idx < NG*64; idx += NB*256) {
        int c = idx & 63, grp = idx >> 6;
        float scl = g_sc1[c];
        float v;
        if (scl >= 0.f) v = fmaxf(g_max1[c*NG2 + 2*grp], g_max1[c*NG2 + 2*grp + 1]);
        else            v = fminf(g_min1[c*NG2 + 2*grp], g_min1[c*NG2 + 2*grp + 1]);
        float lf = fmaxf(fmaf(scl, v, g_bi1[c]), 0.f);
        g_lf1[grp*64+c] = lf;
        int b = grp / G_, g = grp % G_;
        out[OUT_LF_OFF + (b*67 + 3 + c)*15 + g] = lf;
    }
    gbar(1);

    // P2: statsA warp-per-row (one channel per block)
    {
        int c = bid;
        if (t < 67) sw[t] = WA[c*67+t];
        __syncthreads();
        float s = 0.f, q = 0.f;
        for (int row = wp; row < 480; row += 8) {
            int bb = row / 15, r = row % 15, sIdx = r / 3, m = r % 3;
            int gg = c_split[sIdx*3+m];
            const float* lf = g_lf1 + (bb*15+gg)*64;
            float v;
            if (l < 3) {
                int ga = c_split[sIdx*3+0], gb1 = c_split[sIdx*3+1], gc = c_split[sIdx*3+2];
                float c2 = (g_cent[(bb*15+ga)*3+l] + g_cent[(bb*15+gb1)*3+l]
                          + g_cent[(bb*15+gc)*3+l]) * (1.f/3.f);
                float f0 = g_cent[(bb*15+gg)*3+l] - c2;
                v = f0*sw[l] + lf[l+29]*sw[l+32] + lf[l+61]*sw[l+64];
            } else {
                v = lf[l-3]*sw[l] + lf[l+29]*sw[l+32];
            }
            #pragma unroll
            for (int o = 16; o > 0; o >>= 1) v += __shfl_down_sync(0xffffffffu, v, o);
            if (l == 0) { s += v; q = fmaf(v, v, q); }
        }
        if (l == 0) { ps[wp] = s; pq[wp] = q; }
        __syncthreads();
        if (t == 0) {
            float ss = 0.f, qq = 0.f;
            #pragma unroll
            for (int j = 0; j < 8; j++) { ss += ps[j]; qq += pq[j]; }
            float mean = ss * (1.f/480.f);
            float var  = qq * (1.f/480.f) - mean*mean;
            float scl  = gA[c] * rsqrtf(var + 1e-5f);
            g_scaleA[c] = scl;
            g_biasA[c]  = bA[c] - mean*scl;
        }
    }
    gbar(2);

    // P3: gemmAB — two rows per iteration, transposed weights
    for (int pr0 = bid*2; pr0 < 480; pr0 += 2*NB) {
        int hh = t >> 7, c = t & 127;
        int pr = pr0 + hh;
        int bb = pr / 15, r = pr % 15, sIdx = r / 3, m = r % 3;
        int gg = c_split[sIdx*3+m];
        if (c < 3) {
            int ga = c_split[sIdx*3+0], gb1 = c_split[sIdx*3+1], gc = c_split[sIdx*3+2];
            float c2 = (g_cent[(bb*15+ga)*3+c] + g_cent[(bb*15+gb1)*3+c]
                      + g_cent[(bb*15+gc)*3+c]) * (1.f/3.f);
            fA[hh][c] = g_cent[(bb*15+gg)*3+c] - c2;
        }
        if (c < 64) fA[hh][3+c] = g_lf1[(bb*15+gg)*64+c];
        __syncthreads();
        float yA = 0.f;
        #pragma unroll
        for (int i = 0; i < 67; i++) yA = fmaf(g_WAT[i*128+c], fA[hh][i], yA);
        zA[hh][c] = fmaxf(fmaf(g_scaleA[c], yA, g_biasA[c]), 0.f);
        __syncthreads();
        float yB = 0.f;
        #pragma unroll
        for (int i = 0; i < 128; i++) yB = fmaf(g_WBT[i*128+c], zA[hh][i], yB);
        g_yB[pr*128+c] = yB;
        __syncthreads();
    }
    gbar(3);

    // P4: statsB + s3in assembly (one channel per block)
    {
        int c = bid;
        float s = 0.f, q = 0.f;
        for (int p = t; p < 480; p += 256) { float v = g_yB[p*128+c]; s += v; q = fmaf(v,v,q); }
        rs[t] = s; rq[t] = q;
        __syncthreads();
        for (int o = 128; o > 0; o >>= 1) {
            if (t < o) { rs[t] += rs[t+o]; rq[t] += rq[t+o]; }
            __syncthreads();
        }
        if (t == 0) {
            float mean = rs[0] * (1.f/480.f);
            float var  = rq[0] * (1.f/480.f) - mean*mean;
            float scl  = gB[c] * rsqrtf(var + 1e-5f);
            sbx[0] = scl; sbx[1] = bB[c] - mean*scl;
        }
        __syncthreads();
        float scl = sbx[0], bi = sbx[1];
        for (int bs = t; bs < 160; bs += 256) {
            float v0 = g_yB[(bs*3+0)*128+c];
            float v1 = g_yB[(bs*3+1)*128+c];
            float v2 = g_yB[(bs*3+2)*128+c];
            float v  = (scl >= 0.f) ? fmaxf(v0, fmaxf(v1, v2)) : fminf(v0, fminf(v1, v2));
            g_s3in[bs*131 + 3 + c] = fmaxf(fmaf(scl, v, bi), 0.f);
        }
        __syncthreads();
    }
    gbar(4);

    // P5: statsC warp-per-row (two channels per block)
    #pragma unroll
    for (int it = 0; it < 2; it++) {
        int c = bid + it*128;
        if (t < 131) sw[t] = WC[c*131+t];
        __syncthreads();
        float s = 0.f, q = 0.f;
        for (int row = wp; row < 160; row += 8) {
            const float* f = g_s3in + row*131;
            float v = f[l]*sw[l] + f[l+32]*sw[l+32] + f[l+64]*sw[l+64] + f[l+96]*sw[l+96];
            if (l < 3) v = fmaf(f[l+128], sw[l+128], v);
            #pragma unroll
            for (int o = 16; o > 0; o >>= 1) v += __shfl_down_sync(0xffffffffu, v, o);
            if (l == 0) { s += v; q = fmaf(v, v, q); }
        }
        if (l == 0) { ps[wp] = s; pq[wp] = q; }
        __syncthreads();
        if (t == 0) {
            float ss = 0.f, qq = 0.f;
            #pragma unroll
            for (int j = 0; j < 8; j++) { ss += ps[j]; qq += pq[j]; }
            float mean = ss * (1.f/160.f);
            float var  = qq * (1.f/160.f) - mean*mean;
            float scl  = gC[c] * rsqrtf(var + 1e-5f);
            g_scaleC[c] = scl;
            g_biasC[c]  = bC[c] - mean*scl;
        }
        __syncthreads();
    }
    gbar(5);

    // P6: gemmCD (rows 160 over 128 blocks; transposed weights)
    for (int row = bid; row < 160; row += NB) {
        int c = t;
        if (c < 131) fC[c] = g_s3in[row*131+c];
        __syncthreads();
        float yC = 0.f;
        #pragma unroll
        for (int i = 0; i < 131; i++) yC = fmaf(g_WCT[i*256+c], fC[i], yC);
        zC[c] = fmaxf(fmaf(g_scaleC[c], yC, g_biasC[c]), 0.f);
        __syncthreads();
        float yD = 0.f;
        #pragma unroll
        for (int i = 0; i < 256; i++) yD = fmaf(g_WDT[i*256+c], zC[i], yD);
        g_yD[row*256+c] = yD;
        __syncthreads();
    }
    gbar(6);

    // P7: statsD + final output (two channels per block)
    #pragma unroll
    for (int it = 0; it < 2; it++) {
        int c = bid + it*128;
        float s = 0.f, q = 0.f;
        if (t < 160) { float v = g_yD[t*256+c]; s = v; q = v*v; }
        rs[t] = s; rq[t] = q;
        __syncthreads();
        for (int o = 128; o > 0; o >>= 1) {
            if (t < o) { rs[t] += rs[t+o]; rq[t] += rq[t+o]; }
            __syncthreads();
        }
        if (t == 0) {
            float mean = rs[0] * (1.f/160.f);
            float var  = rq[0] * (1.f/160.f) - mean*mean;
            float scl  = gD[c] * rsqrtf(var + 1e-5f);
            sbx[0] = scl; sbx[1] = bD[c] - mean*scl;
        }
        __syncthreads();
        float scl = sbx[0], bi = sbx[1];
        if (t < 32) {
            float v = (scl >= 0.f) ? -3.402823e38f : 3.402823e38f;
            #pragma unroll
            for (int ss = 0; ss < 5; ss++) {
                float y = g_yD[(t*5+ss)*256+c];
                v = (scl >= 0.f) ? fmaxf(v, y) : fminf(v, y);
            }
            out[t*256+c] = fmaxf(fmaf(scl, v, bi), 0.f);
        }
        __syncthreads();
    }
}

// ---------------- launch ----------------
extern "C" void kernel_launch(void* const* d_in, const int* in_sizes, int n_in,
                              void* d_out, int out_size) {
    const float* x      = (const float*)d_in[0];
    const float* la0_w0 = (const float*)d_in[1];
    const float* la0_g0 = (const float*)d_in[2];
    const float* la0_b0 = (const float*)d_in[3];
    const float* la0_w1 = (const float*)d_in[4];
    const float* la0_g1 = (const float*)d_in[5];
    const float* la0_b1 = (const float*)d_in[6];
    const float* la1_w0 = (const float*)d_in[7];
    const float* la1_g0 = (const float*)d_in[8];
    const float* la1_b0 = (const float*)d_in[9];
    const float* la1_w1 = (const float*)d_in[10];
    const float* la1_g1 = (const float*)d_in[11];
    const float* la1_b1 = (const float*)d_in[12];
    const float* la2_w0 = (const float*)d_in[13];
    const float* la2_g0 = (const float*)d_in[14];
    const float* la2_b0 = (const float*)d_in[15];
    const float* la2_w1 = (const float*)d_in[16];
    const float* la2_g1 = (const float*)d_in[17];
    const float* la2_b1 = (const float*)d_in[18];
    float* out = (float*)d_out;

    const int SMEM_MAIN = (2048 + 4608 + 256 + 4) * 4;
    cudaFuncSetAttribute(k_main, cudaFuncAttributeMaxDynamicSharedMemorySize, SMEM_MAIN);

    k_centroid<<<NG, 256>>>(x, out);
    k_bn0<<<1, 192>>>(la0_w0, la0_g0, la0_b0);
    k_main<<<NG2, 256, SMEM_MAIN>>>(x, la0_w1);
    k_tail<<<NB, 256>>>(la0_g1, la0_b1,
                        la1_w0, la1_g0, la1_b0,
                        la1_w1, la1_g1, la1_b1,
                        la2_w0, la2_g0, la2_b0,
                        la2_w1, la2_g1, la2_b1,
                        out);
}

// round 15
// speedup vs baseline: 1.1312x; 1.1312x over previous
#include <cuda_runtime.h>
#include <cuda_fp16.h>
#include <math.h>
#include <stdint.h>

#define B_   32
#define G_   15
#define K_   2048
#define NG   480
#define NG2  960
#define NPTS 983040
#define TILE_P 128
#define ZSTR 36
#define OUT_LF_OFF 8192

__constant__ int c_split[15] = {0,1,8, 2,4,6, 3,5,7, 9,11,13, 10,12,14};

// ---------------- device scratch ----------------
__device__ float  g_cent[NG*3];
__device__ float  g_S0p[NG*6];
__device__ float4 g_w0s[64];
__device__ float  g_max1[64*NG2];
__device__ float  g_min1[64*NG2];
__device__ float  g_psum1[64*NG2];
__device__ float  g_psq1[64*NG2];
__device__ float  g_lf1[NG*64];
__device__ float  g_yB[480*128];
__device__ float  g_scaleA[128];
__device__ float  g_biasA[128];
__device__ float  g_s3in[160*131];
__device__ float  g_yD[160*256];
__device__ float  g_scaleC[256];
__device__ float  g_biasC[256];
__device__ float  g_WAT[67*128];
__device__ float  g_WBT[128*128];
__device__ float  g_WCT[131*256];
__device__ float  g_WDT[256*256];

__device__ __forceinline__ uint32_t h2u(__half2 h) { uint32_t u; memcpy(&u, &h, 4); return u; }
__device__ __forceinline__ uint32_t smem_u32(const void* p) {
    uint32_t a;
    asm("{ .reg .u64 tmp; cvta.to.shared.u64 tmp, %1; cvt.u32.u64 %0, tmp; }" : "=r"(a) : "l"(p));
    return a;
}

#define MMA_F16(d, a, b)                                                      \
    asm volatile(                                                             \
        "mma.sync.aligned.m16n8k16.row.col.f32.f16.f16.f32 "                  \
        "{%0,%1,%2,%3}, {%4,%5,%6,%7}, {%8,%9}, {%0,%1,%2,%3};"               \
        : "+f"((d)[0]), "+f"((d)[1]), "+f"((d)[2]), "+f"((d)[3])              \
        : "r"((a)[0]), "r"((a)[1]), "r"((a)[2]), "r"((a)[3]),                 \
          "r"((b)[0]), "r"((b)[1]))

#define LDM_X4(r, addr)                                                       \
    asm volatile("ldmatrix.sync.aligned.m8n8.x4.shared.b16 {%0,%1,%2,%3}, [%4];" \
        : "=r"((r)[0]), "=r"((r)[1]), "=r"((r)[2]), "=r"((r)[3]) : "r"(addr))

// ---------------- weight transposes (off critical path) ----------------
__global__ void k_wT(const float* __restrict__ WA, const float* __restrict__ WB,
                     const float* __restrict__ WC, const float* __restrict__ WD) {
    int t = blockIdx.x*256 + threadIdx.x;
    if (t < 67*128) {
        int i = t >> 7, c = t & 127;
        g_WAT[t] = WA[c*67 + i];
    }
    int t2 = t - 67*128;
    if (t2 >= 0 && t2 < 128*128) {
        int i = t2 >> 7, c = t2 & 127;
        g_WBT[t2] = WB[c*128 + i];
    }
    int t3 = t2 - 128*128;
    if (t3 >= 0 && t3 < 131*256) {
        int i = t3 >> 8, c = t3 & 255;
        g_WCT[t3] = WC[c*131 + i];
    }
    int t4 = t3 - 131*256;
    if (t4 >= 0 && t4 < 256*256) {
        int i = t4 >> 8, c = t4 & 255;
        g_WDT[t4] = WD[c*256 + i];
    }
}

// ---------------- stage 1: centroids + 3x3 second-moment partials ----------------
__global__ void k_centroid(const float* __restrict__ x, float* __restrict__ out) {
    __shared__ float red[9*256];
    int blk = blockIdx.x, t = threadIdx.x;
    const float4* xg4 = (const float4*)(x + (size_t)blk * (K_*3));
    float s0=0,s1=0,s2=0,m00=0,m01=0,m02=0,m11=0,m12=0,m22=0;
    #pragma unroll
    for (int it = 0; it < 2; it++) {
        int cidx = t + it*256;
        const float4* cp = xg4 + cidx*3;
        float4 A = cp[0], Bv = cp[1], C = cp[2];
        float px[4] = {A.x, A.w, Bv.z, C.y};
        float py[4] = {A.y, Bv.x, Bv.w, C.z};
        float pz[4] = {A.z, Bv.y, C.x, C.w};
        #pragma unroll
        for (int j = 0; j < 4; j++) {
            float a = px[j], b = py[j], c = pz[j];
            s0+=a; s1+=b; s2+=c;
            m00=fmaf(a,a,m00); m01=fmaf(a,b,m01); m02=fmaf(a,c,m02);
            m11=fmaf(b,b,m11); m12=fmaf(b,c,m12); m22=fmaf(c,c,m22);
        }
    }
    red[0*256+t]=s0; red[1*256+t]=s1; red[2*256+t]=s2;
    red[3*256+t]=m00; red[4*256+t]=m01; red[5*256+t]=m02;
    red[6*256+t]=m11; red[7*256+t]=m12; red[8*256+t]=m22;
    __syncthreads();
    for (int s = 128; s > 0; s >>= 1) {
        if (t < s) {
            #pragma unroll
            for (int j = 0; j < 9; j++) red[j*256+t] += red[j*256+t+s];
        }
        __syncthreads();
    }
    if (t == 0) {
        const float invK = 1.0f / (float)K_;
        float C0 = red[0]*invK, C1 = red[256]*invK, C2 = red[512]*invK;
        g_cent[blk*3+0]=C0; g_cent[blk*3+1]=C1; g_cent[blk*3+2]=C2;
        g_S0p[blk*6+0] = red[3*256] - (float)K_*C0*C0;
        g_S0p[blk*6+1] = red[4*256] - (float)K_*C0*C1;
        g_S0p[blk*6+2] = red[5*256] - (float)K_*C0*C2;
        g_S0p[blk*6+3] = red[6*256] - (float)K_*C1*C1;
        g_S0p[blk*6+4] = red[7*256] - (float)K_*C1*C2;
        g_S0p[blk*6+5] = red[8*256] - (float)K_*C2*C2;
        int b = blk / G_, g = blk % G_;
        out[OUT_LF_OFF + (b*67+0)*15 + g] = C0;
        out[OUT_LF_OFF + (b*67+1)*15 + g] = C1;
        out[OUT_LF_OFF + (b*67+2)*15 + g] = C2;
    }
}

// layer-0 BN fold + rel3 channels of s3in
__global__ void k_bn0(const float* __restrict__ W0, const float* __restrict__ g0,
                      const float* __restrict__ b0) {
    __shared__ float S[6];
    int t = threadIdx.x, w = t >> 5, lane = t & 31;
    if (w < 6) {
        float s = 0.f;
        for (int p = lane; p < NG; p += 32) s += g_S0p[p*6 + w];
        #pragma unroll
        for (int o = 16; o > 0; o >>= 1) s += __shfl_down_sync(0xffffffffu, s, o);
        if (lane == 0) S[w] = s;
    }
    if (t < 160) {
        int bb = t / 5, sIdx = t % 5;
        float c2s[3] = {0,0,0}, c3[3] = {0,0,0};
        #pragma unroll
        for (int ss = 0; ss < 5; ss++) {
            int ga = c_split[ss*3+0], gb1 = c_split[ss*3+1], gc = c_split[ss*3+2];
            #pragma unroll
            for (int i = 0; i < 3; i++) {
                float v = (g_cent[(bb*15+ga)*3+i] + g_cent[(bb*15+gb1)*3+i]
                         + g_cent[(bb*15+gc)*3+i]) * (1.f/3.f);
                c3[i] += v;
                if (ss == sIdx) c2s[i] = v;
            }
        }
        #pragma unroll
        for (int i = 0; i < 3; i++)
            g_s3in[t*131 + i] = c2s[i] - c3[i]*0.2f;
    }
    __syncthreads();
    if (t < 64) {
        float w0 = W0[t*3+0], w1 = W0[t*3+1], w2 = W0[t*3+2];
        float var = (w0*w0*S[0] + w1*w1*S[3] + w2*w2*S[5]
                   + 2.f*(w0*w1*S[1] + w0*w2*S[2] + w1*w2*S[4])) * (1.0f/(float)NPTS);
        float scl = g0[t] * rsqrtf(var + 1e-5f);
        g_w0s[t] = make_float4(scl*w0, scl*w1, scl*w2, b0[t]);
    }
}

// ---------------- stage 1 main pass: hi-only HMMA via ldmatrix + exact argmax refine ----------------
__global__ void __launch_bounds__(256,2) k_main(const float* __restrict__ x,
                                                const float* __restrict__ W1) {
    extern __shared__ float smem[];
    uint32_t* sWhi = (uint32_t*)smem;
    uint32_t* sZ   = sWhi + 2048;
    float*    sRedV = (float*)sZ;
    int*      sRedI = (int*)(sZ + 2048);
    int*      sBI   = (int*)(sZ + 4096);
    float4*   sW0s  = (float4*)(sZ + 4608);
    float*    sCen  = (float*)(sW0s + 64);

    const int blk = blockIdx.x, t = threadIdx.x;
    const int grp = blk >> 1, half = blk & 1;
    const int lane = t & 31, w = t >> 5;
    const int wm = w >> 1, wn = w & 1;
    const int gid = lane >> 2, tig = lane & 3;

    for (int idx = t; idx < 2048; idx += 256) {
        int n = idx >> 5, kk = idx & 31;
        sWhi[idx] = h2u(__floats2half2_rn(W1[n*64 + 2*kk], W1[n*64 + 2*kk + 1]));
    }
    if (t < 64) sW0s[t] = g_w0s[t];
    if (t < 3)  sCen[t] = g_cent[grp*3 + t];
    __syncthreads();

    uint32_t bh[4][4][2];
    {
        const int n0 = wn * 32;
        #pragma unroll
        for (int nt = 0; nt < 4; nt++)
            #pragma unroll
            for (int k0 = 0; k0 < 4; k0++) {
                const int base = (n0 + nt*8 + gid)*32 + k0*8 + tig;
                bh[nt][k0][0] = sWhi[base];
                bh[nt][k0][1] = sWhi[base + 4];
            }
    }

    const float* xg = x + ((size_t)grp * K_ + half * 1024) * 3;
    const float c0 = sCen[0], c1 = sCen[1], c2v = sCen[2];
    const int h  = w >> 2;
    const int p1 = (w & 3) * 32 + lane;

    const int lrow = (lane & 7) + ((lane & 8) ? 8 : 0);
    const int lcol = (lane & 16) ? 4 : 0;
    const uint32_t zbase = smem_u32(sZ);
    const int ptb = wm * 32;
    const uint32_t a_addr0 = zbase + (uint32_t)(((ptb + lrow)*ZSTR + lcol) * 4);
    const uint32_t a_addr1 = a_addr0 + 16*ZSTR*4;

    float mx[8], mn[8], sm[8], sq[8];
    int   xini[8];
    #pragma unroll
    for (int s = 0; s < 8; s++) {
        mx[s]=-3.402823e38f; mn[s]=3.402823e38f; sm[s]=0.f; sq[s]=0.f; xini[s]=0;
    }

    for (int tile = 0; tile < 8; tile++) {
        {
            const float* xp = xg + (size_t)(tile*128 + p1)*3;
            float r0 = xp[0]-c0, r1 = xp[1]-c1, r2 = xp[2]-c2v;
            uint32_t zh2[16];
            #pragma unroll
            for (int j = 0; j < 16; j++) {
                float4 qa = sW0s[h*32 + 2*j];
                float4 qb = sW0s[h*32 + 2*j + 1];
                float za = fmaxf(fmaf(qa.x, r0, fmaf(qa.y, r1, fmaf(qa.z, r2, qa.w))), 0.f);
                float zb = fmaxf(fmaf(qb.x, r0, fmaf(qb.y, r1, fmaf(qb.z, r2, qb.w))), 0.f);
                zh2[j] = h2u(__floats2half2_rn(za, zb));
            }
            uint4* zh = (uint4*)(sZ + p1*ZSTR + h*16);
            #pragma unroll
            for (int j4 = 0; j4 < 4; j4++)
                zh[j4] = make_uint4(zh2[j4*4], zh2[j4*4+1], zh2[j4*4+2], zh2[j4*4+3]);
        }
        __syncthreads();

        float acc[2][4][4];
        #pragma unroll
        for (int m = 0; m < 2; m++)
            #pragma unroll
            for (int nt = 0; nt < 4; nt++)
                #pragma unroll
                for (int r = 0; r < 4; r++) acc[m][nt][r] = 0.f;

        #pragma unroll
        for (int k0 = 0; k0 < 4; k0++) {
            uint32_t ah[2][4];
            LDM_X4(ah[0], a_addr0 + k0*32);
            LDM_X4(ah[1], a_addr1 + k0*32);
            #pragma unroll
            for (int m = 0; m < 2; m++)
                #pragma unroll
                for (int nt = 0; nt < 4; nt++)
                    MMA_F16(acc[m][nt], ah[m], bh[nt][k0]);
        }

        #pragma unroll
        for (int m = 0; m < 2; m++)
            #pragma unroll
            for (int nt = 0; nt < 4; nt++)
                #pragma unroll
                for (int r = 0; r < 4; r++) {
                    float v = acc[m][nt][r];
                    int s = nt*2 + (r & 1);
                    int pidx = tile*128 + wm*32 + m*16 + gid + (r>>1)*8;
                    if (v > mx[s]) { mx[s] = v; xini[s] = (xini[s] & 0xFFFF0000) | pidx; }
                    if (v < mn[s]) { mn[s] = v; xini[s] = (xini[s] & 0x0000FFFF) | (pidx << 16); }
                    sm[s] += v;
                    sq[s] = fmaf(v, v, sq[s]);
                }
        __syncthreads();
    }

    const int slot = wm*8 + gid;
    #pragma unroll
    for (int s = 0; s < 8; s++) {
        int ch = wn*32 + (s>>1)*8 + 2*tig + (s&1);
        sRedV[ch*32 + slot] = mx[s];
        sRedI[ch*32 + slot] = xini[s] & 0xFFFF;
    }
    __syncthreads();
    if (t < 64) {
        float v = sRedV[t*32]; int bi = sRedI[t*32];
        #pragma unroll
        for (int j = 1; j < 32; j++) {
            float u = sRedV[t*32+j];
            if (u > v) { v = u; bi = sRedI[t*32+j]; }
        }
        sBI[t] = bi;
    }
    __syncthreads();
    #pragma unroll
    for (int s = 0; s < 8; s++) {
        int ch = wn*32 + (s>>1)*8 + 2*tig + (s&1);
        sRedV[ch*32 + slot] = mn[s];
        sRedI[ch*32 + slot] = (xini[s] >> 16) & 0xFFFF;
    }
    __syncthreads();
    if (t < 64) {
        float v = sRedV[t*32]; int bi = sRedI[t*32];
        #pragma unroll
        for (int j = 1; j < 32; j++) {
            float u = sRedV[t*32+j];
            if (u < v) { v = u; bi = sRedI[t*32+j]; }
        }
        sBI[64 + t] = bi;
    }
    __syncthreads();
    #pragma unroll
    for (int s = 0; s < 8; s++)
        sRedV[(wn*32 + (s>>1)*8 + 2*tig + (s&1))*32 + slot] = sm[s];
    __syncthreads();
    if (t < 64) {
        float v = 0.f;
        #pragma unroll
        for (int j = 0; j < 32; j++) v += sRedV[t*32+j];
        g_psum1[t*NG2 + blk] = v;
    }
    __syncthreads();
    #pragma unroll
    for (int s = 0; s < 8; s++)
        sRedV[(wn*32 + (s>>1)*8 + 2*tig + (s&1))*32 + slot] = sq[s];
    __syncthreads();
    if (t < 64) {
        float v = 0.f;
        #pragma unroll
        for (int j = 0; j < 32; j++) v += sRedV[t*32+j];
        g_psq1[t*NG2 + blk] = v;
    }

    if (t < 128) {
        int c = t & 63;
        int p = sBI[t];
        const float* xp = xg + (size_t)p*3;
        float r0 = xp[0]-c0, r1 = xp[1]-c1, r2 = xp[2]-c2v;
        const float4* w4 = (const float4*)(W1 + c*64);
        float y = 0.f;
        #pragma unroll 4
        for (int j = 0; j < 16; j++) {
            float4 wv = w4[j];
            float4 q0 = sW0s[4*j+0], q1 = sW0s[4*j+1], q2 = sW0s[4*j+2], q3 = sW0s[4*j+3];
            float z0 = fmaxf(fmaf(q0.x, r0, fmaf(q0.y, r1, fmaf(q0.z, r2, q0.w))), 0.f);
            float z1 = fmaxf(fmaf(q1.x, r0, fmaf(q1.y, r1, fmaf(q1.z, r2, q1.w))), 0.f);
            float z2 = fmaxf(fmaf(q2.x, r0, fmaf(q2.y, r1, fmaf(q2.z, r2, q2.w))), 0.f);
            float z3 = fmaxf(fmaf(q3.x, r0, fmaf(q3.y, r1, fmaf(q3.z, r2, q3.w))), 0.f);
            y = fmaf(wv.x, z0, y); y = fmaf(wv.y, z1, y);
            y = fmaf(wv.z, z2, y); y = fmaf(wv.w, z3, y);
        }
        if (t < 64) g_max1[c*NG2 + blk] = y;
        else        g_min1[c*NG2 + blk] = y;
    }
}

// ---------------- fused layer-1 BN stats + lf1 + local_features ----------------
__global__ void k_bn1lf1(const float* __restrict__ g1, const float* __restrict__ b1,
                         float* __restrict__ out) {
    __shared__ float rs[256], rq[256], s_sc[1], s_bi[1];
    int c = blockIdx.x, t = threadIdx.x;
    float s = 0.f, q = 0.f;
    for (int p = t; p < NG2; p += 256) { s += g_psum1[c*NG2+p]; q += g_psq1[c*NG2+p]; }
    rs[t] = s; rq[t] = q;
    __syncthreads();
    for (int o = 128; o > 0; o >>= 1) {
        if (t < o) { rs[t] += rs[t+o]; rq[t] += rq[t+o]; }
        __syncthreads();
    }
    if (t == 0) {
        float mean = rs[0] * (1.0f/(float)NPTS);
        float var  = rq[0] * (1.0f/(float)NPTS) - mean*mean;
        float scl  = g1[c] * rsqrtf(var + 1e-5f);
        s_sc[0] = scl; s_bi[0] = b1[c] - mean*scl;
    }
    __syncthreads();
    float scl = s_sc[0], bi = s_bi[0];
    for (int grp = t; grp < NG; grp += 256) {
        float v;
        if (scl >= 0.f) v = fmaxf(g_max1[c*NG2 + 2*grp], g_max1[c*NG2 + 2*grp + 1]);
        else            v = fminf(g_min1[c*NG2 + 2*grp], g_min1[c*NG2 + 2*grp + 1]);
        float lf = fmaxf(fmaf(scl, v, bi), 0.f);
        g_lf1[grp*64+c] = lf;
        int b = grp / G_, g = grp % G_;
        out[OUT_LF_OFF + (b*67 + 3 + c)*15 + g] = lf;
    }
}

// layer-A BN stats: warp-per-row, lanes split the 67-dot (coalesced lf1 reads)
__global__ void k_statsA_w(const float* __restrict__ W,
                           const float* __restrict__ g, const float* __restrict__ b) {
    __shared__ float sw[67], ps[8], pq[8];
    int c = blockIdx.x, t = threadIdx.x; // 128 blocks x 256
    int wp = t >> 5, l = t & 31;
    if (t < 67) sw[t] = W[c*67+t];
    __syncthreads();
    float s = 0.f, q = 0.f;
    for (int row = wp; row < 480; row += 8) {
        int bb = row / 15, r = row % 15, sIdx = r / 3, m = r % 3;
        int gg = c_split[sIdx*3+m];
        const float* lf = g_lf1 + (bb*15+gg)*64;
        float v;
        if (l < 3) {
            int ga = c_split[sIdx*3+0], gb1 = c_split[sIdx*3+1], gc = c_split[sIdx*3+2];
            float c2 = (g_cent[(bb*15+ga)*3+l] + g_cent[(bb*15+gb1)*3+l]
                      + g_cent[(bb*15+gc)*3+l]) * (1.f/3.f);
            float f0 = g_cent[(bb*15+gg)*3+l] - c2;
            v = f0*sw[l] + lf[l+29]*sw[l+32] + lf[l+61]*sw[l+64];
        } else {
            v = lf[l-3]*sw[l] + lf[l+29]*sw[l+32];
        }
        #pragma unroll
        for (int o = 16; o > 0; o >>= 1) v += __shfl_down_sync(0xffffffffu, v, o);
        if (l == 0) { s += v; q = fmaf(v, v, q); }
    }
    if (l == 0) { ps[wp] = s; pq[wp] = q; }
    __syncthreads();
    if (t == 0) {
        float ss = 0.f, qq = 0.f;
        #pragma unroll
        for (int j = 0; j < 8; j++) { ss += ps[j]; qq += pq[j]; }
        float mean = ss * (1.f/480.f);
        float var  = qq * (1.f/480.f) - mean*mean;
        float scl  = g[c] * rsqrtf(var + 1e-5f);
        g_scaleA[c] = scl;
        g_biasA[c]  = b[c] - mean*scl;
    }
}

// fused gemmA + BN-relu + gemmB; transposed weights -> coalesced
__global__ void k_gemmAB() {
    __shared__ float f[67], z[128];
    int p = blockIdx.x, c = threadIdx.x;
    int bb = p / 15, r = p % 15, sIdx = r / 3, m = r % 3;
    int gg = c_split[sIdx*3+m];
    if (c < 3) {
        int ga = c_split[sIdx*3+0], gb1 = c_split[sIdx*3+1], gc = c_split[sIdx*3+2];
        float c2 = (g_cent[(bb*15+ga)*3+c] + g_cent[(bb*15+gb1)*3+c]
                  + g_cent[(bb*15+gc)*3+c]) * (1.f/3.f);
        f[c] = g_cent[(bb*15+gg)*3+c] - c2;
    }
    if (c < 64) f[3+c] = g_lf1[(bb*15+gg)*64+c];
    __syncthreads();
    float yA = 0.f;
    #pragma unroll
    for (int i = 0; i < 67; i++) yA = fmaf(g_WAT[i*128+c], f[i], yA);
    z[c] = fmaxf(fmaf(g_scaleA[c], yA, g_biasA[c]), 0.f);
    __syncthreads();
    float yB = 0.f;
    #pragma unroll
    for (int i = 0; i < 128; i++) yB = fmaf(g_WBT[i*128+c], z[i], yB);
    g_yB[p*128+c] = yB;
}

// fused statsB + s3in assembly
__global__ void k_statsB_s3in(const float* __restrict__ g, const float* __restrict__ b) {
    __shared__ float rs[256], rq[256], s_sc[1], s_bi[1];
    int c = blockIdx.x, t = threadIdx.x;
    float s = 0.f, q = 0.f;
    for (int p = t; p < 480; p += 256) { float v = g_yB[p*128+c]; s += v; q = fmaf(v,v,q); }
    rs[t] = s; rq[t] = q;
    __syncthreads();
    for (int o = 128; o > 0; o >>= 1) {
        if (t < o) { rs[t] += rs[t+o]; rq[t] += rq[t+o]; }
        __syncthreads();
    }
    if (t == 0) {
        float mean = rs[0] * (1.f/480.f);
        float var  = rq[0] * (1.f/480.f) - mean*mean;
        float scl  = g[c] * rsqrtf(var + 1e-5f);
        s_sc[0] = scl; s_bi[0] = b[c] - mean*scl;
    }
    __syncthreads();
    float scl = s_sc[0], bi = s_bi[0];
    for (int bs = t; bs < 160; bs += 256) {
        float v0 = g_yB[(bs*3+0)*128+c];
        float v1 = g_yB[(bs*3+1)*128+c];
        float v2 = g_yB[(bs*3+2)*128+c];
        float v  = (scl >= 0.f) ? fmaxf(v0, fmaxf(v1, v2)) : fminf(v0, fminf(v1, v2));
        g_s3in[bs*131 + 3 + c] = fmaxf(fmaf(scl, v, bi), 0.f);
    }
}

// layer-C BN stats: warp-per-row, lanes split the 131-dot (coalesced s3in reads)
__global__ void k_statsC_w(const float* __restrict__ W,
                           const float* __restrict__ g, const float* __restrict__ b) {
    __shared__ float sw[131], ps[8], pq[8];
    int c = blockIdx.x, t = threadIdx.x; // 256 blocks x 256
    int wp = t >> 5, l = t & 31;
    if (t < 131) sw[t] = W[c*131+t];
    __syncthreads();
    float s = 0.f, q = 0.f;
    for (int row = wp; row < 160; row += 8) {
        const float* f = g_s3in + row*131;
        float v = f[l]*sw[l] + f[l+32]*sw[l+32] + f[l+64]*sw[l+64] + f[l+96]*sw[l+96];
        if (l < 3) v = fmaf(f[l+128], sw[l+128], v);
        #pragma unroll
        for (int o = 16; o > 0; o >>= 1) v += __shfl_down_sync(0xffffffffu, v, o);
        if (l == 0) { s += v; q = fmaf(v, v, q); }
    }
    if (l == 0) { ps[wp] = s; pq[wp] = q; }
    __syncthreads();
    if (t == 0) {
        float ss = 0.f, qq = 0.f;
        #pragma unroll
        for (int j = 0; j < 8; j++) { ss += ps[j]; qq += pq[j]; }
        float mean = ss * (1.f/160.f);
        float var  = qq * (1.f/160.f) - mean*mean;
        float scl  = g[c] * rsqrtf(var + 1e-5f);
        g_scaleC[c] = scl;
        g_biasC[c]  = b[c] - mean*scl;
    }
}

// fused gemmC + BN-relu + gemmD; transposed weights -> coalesced
__global__ void k_gemmCD() {
    __shared__ float f[131], z[256];
    int bs = blockIdx.x, c = threadIdx.x;
    if (c < 131) f[c] = g_s3in[bs*131+c];
    __syncthreads();
    float yC = 0.f;
    #pragma unroll
    for (int i = 0; i < 131; i++) yC = fmaf(g_WCT[i*256+c], f[i], yC);
    z[c] = fmaxf(fmaf(g_scaleC[c], yC, g_biasC[c]), 0.f);
    __syncthreads();
    float yD = 0.f;
    #pragma unroll
    for (int i = 0; i < 256; i++) yD = fmaf(g_WDT[i*256+c], z[i], yD);
    g_yD[bs*256+c] = yD;
}

// fused statsD + final output
__global__ void k_statsD_out(const float* __restrict__ g, const float* __restrict__ b,
                             float* __restrict__ out) {
    __shared__ float rs[256], rq[256], s_sc[1], s_bi[1];
    int c = blockIdx.x, t = threadIdx.x;
    float s = 0.f, q = 0.f;
    if (t < 160) { float v = g_yD[t*256+c]; s = v; q = v*v; }
    rs[t] = s; rq[t] = q;
    __syncthreads();
    for (int o = 128; o > 0; o >>= 1) {
        if (t < o) { rs[t] += rs[t+o]; rq[t] += rq[t+o]; }
        __syncthreads();
    }
    if (t == 0) {
        float mean = rs[0] * (1.f/160.f);
        float var  = rq[0] * (1.f/160.f) - mean*mean;
        float scl  = g[c] * rsqrtf(var + 1e-5f);
        s_sc[0] = scl; s_bi[0] = b[c] - mean*scl;
    }
    __syncthreads();
    float scl = s_sc[0], bi = s_bi[0];
    if (t < 32) {
        float v = (scl >= 0.f) ? -3.402823e38f : 3.402823e38f;
        #pragma unroll
        for (int ss = 0; ss < 5; ss++) {
            float y = g_yD[(t*5+ss)*256+c];
            v = (scl >= 0.f) ? fmaxf(v, y) : fminf(v, y);
        }
        out[t*256+c] = fmaxf(fmaf(scl, v, bi), 0.f);
    }
}

// ---------------- launch ----------------
extern "C" void kernel_launch(void* const* d_in, const int* in_sizes, int n_in,
                              void* d_out, int out_size) {
    const float* x      = (const float*)d_in[0];
    const float* la0_w0 = (const float*)d_in[1];
    const float* la0_g0 = (const float*)d_in[2];
    const float* la0_b0 = (const float*)d_in[3];
    const float* la0_w1 = (const float*)d_in[4];
    const float* la0_g1 = (const float*)d_in[5];
    const float* la0_b1 = (const float*)d_in[6];
    const float* la1_w0 = (const float*)d_in[7];
    const float* la1_g0 = (const float*)d_in[8];
    const float* la1_b0 = (const float*)d_in[9];
    const float* la1_w1 = (const float*)d_in[10];
    const float* la1_g1 = (const float*)d_in[11];
    const float* la1_b1 = (const float*)d_in[12];
    const float* la2_w0 = (const float*)d_in[13];
    const float* la2_g0 = (const float*)d_in[14];
    const float* la2_b0 = (const float*)d_in[15];
    const float* la2_w1 = (const float*)d_in[16];
    const float* la2_g1 = (const float*)d_in[17];
    const float* la2_b1 = (const float*)d_in[18];
    float* out = (float*)d_out;

    const int SMEM_MAIN = (2048 + 4608 + 256 + 4) * 4;
    cudaFuncSetAttribute(k_main, cudaFuncAttributeMaxDynamicSharedMemorySize, SMEM_MAIN);

    k_wT<<<485, 256>>>(la1_w0, la1_w1, la2_w0, la2_w1);
    k_centroid<<<NG, 256>>>(x, out);
    k_bn0<<<1, 192>>>(la0_w0, la0_g0, la0_b0);
    k_main<<<NG2, 256, SMEM_MAIN>>>(x, la0_w1);
    k_bn1lf1<<<64, 256>>>(la0_g1, la0_b1, out);
    k_statsA_w<<<128, 256>>>(la1_w0, la1_g0, la1_b0);
    k_gemmAB<<<480, 128>>>();
    k_statsB_s3in<<<128, 256>>>(la1_g1, la1_b1);
    k_statsC_w<<<256, 256>>>(la2_w0, la2_g0, la2_b0);
    k_gemmCD<<<160, 256>>>();
    k_statsD_out<<<256, 256>>>(la2_g1, la2_b1, out);
}

// round 16
// speedup vs baseline: 1.2520x; 1.1067x over previous
#include <cuda_runtime.h>
#include <cuda_fp16.h>
#include <math.h>
#include <stdint.h>

#define B_   32
#define G_   15
#define K_   2048
#define NG   480
#define NG2  960
#define NPTS 983040
#define TILE_P 128
#define ZSTR 36
#define OUT_LF_OFF 8192
#define NT   244           // transpose helper blocks appended to k_centroid grid

__constant__ int c_split[15] = {0,1,8, 2,4,6, 3,5,7, 9,11,13, 10,12,14};

// ---------------- device scratch ----------------
__device__ float  g_cent[NG*3];
__device__ float  g_S0p[NG*6];
__device__ float4 g_w0s[64];
__device__ float  g_max1[64*NG2];   // channel-major [c][blk], refined exact values
__device__ float  g_psum1[64*NG2];
__device__ float  g_psq1[64*NG2];
__device__ float  g_lf1[NG*64];
__device__ float  g_yB[480*128];
__device__ float  g_scaleA[128];
__device__ float  g_biasA[128];
__device__ float  g_s3in[160*131];
__device__ float  g_yD[160*256];
__device__ float  g_scaleC[256];
__device__ float  g_biasC[256];
__device__ float  g_WAT[67*128];
__device__ float  g_WBT[128*128];
__device__ float  g_WCT[131*256];
__device__ float  g_WDT[256*256];

__device__ __forceinline__ uint32_t h2u(__half2 h) { uint32_t u; memcpy(&u, &h, 4); return u; }
__device__ __forceinline__ uint32_t smem_u32(const void* p) {
    uint32_t a;
    asm("{ .reg .u64 tmp; cvta.to.shared.u64 tmp, %1; cvt.u32.u64 %0, tmp; }" : "=r"(a) : "l"(p));
    return a;
}

#define MMA_F16(d, a, b)                                                      \
    asm volatile(                                                             \
        "mma.sync.aligned.m16n8k16.row.col.f32.f16.f16.f32 "                  \
        "{%0,%1,%2,%3}, {%4,%5,%6,%7}, {%8,%9}, {%0,%1,%2,%3};"               \
        : "+f"((d)[0]), "+f"((d)[1]), "+f"((d)[2]), "+f"((d)[3])              \
        : "r"((a)[0]), "r"((a)[1]), "r"((a)[2]), "r"((a)[3]),                 \
          "r"((b)[0]), "r"((b)[1]))

#define LDM_X4(r, addr)                                                       \
    asm volatile("ldmatrix.sync.aligned.m8n8.x4.shared.b16 {%0,%1,%2,%3}, [%4];" \
        : "=r"((r)[0]), "=r"((r)[1]), "=r"((r)[2]), "=r"((r)[3]) : "r"(addr))

// ---------------- stage 1: centroids + moments (blocks <NG) | weight transposes (rest) ----------------
__global__ void k_centroid(const float* __restrict__ x, float* __restrict__ out,
                           const float* __restrict__ WA, const float* __restrict__ WB,
                           const float* __restrict__ WC, const float* __restrict__ WD) {
    __shared__ float red[9*256];
    int blk = blockIdx.x, t = threadIdx.x;
    if (blk >= NG) {
        // weight transposes, grid-stride over appended blocks
        const int base = (blk - NG)*256 + t;
        const int stride = NT*256;
        for (int i = base; i < 67*128; i += stride)  { int k = i>>7, c = i&127; g_WAT[i] = WA[c*67+k]; }
        for (int i = base; i < 128*128; i += stride) { int k = i>>7, c = i&127; g_WBT[i] = WB[c*128+k]; }
        for (int i = base; i < 131*256; i += stride) { int k = i>>8, c = i&255; g_WCT[i] = WC[c*131+k]; }
        for (int i = base; i < 256*256; i += stride) { int k = i>>8, c = i&255; g_WDT[i] = WD[c*256+k]; }
        return;
    }
    const float4* xg4 = (const float4*)(x + (size_t)blk * (K_*3));
    float s0=0,s1=0,s2=0,m00=0,m01=0,m02=0,m11=0,m12=0,m22=0;
    #pragma unroll
    for (int it = 0; it < 2; it++) {
        int cidx = t + it*256;
        const float4* cp = xg4 + cidx*3;
        float4 A = cp[0], Bv = cp[1], C = cp[2];
        float px[4] = {A.x, A.w, Bv.z, C.y};
        float py[4] = {A.y, Bv.x, Bv.w, C.z};
        float pz[4] = {A.z, Bv.y, C.x, C.w};
        #pragma unroll
        for (int j = 0; j < 4; j++) {
            float a = px[j], b = py[j], c = pz[j];
            s0+=a; s1+=b; s2+=c;
            m00=fmaf(a,a,m00); m01=fmaf(a,b,m01); m02=fmaf(a,c,m02);
            m11=fmaf(b,b,m11); m12=fmaf(b,c,m12); m22=fmaf(c,c,m22);
        }
    }
    red[0*256+t]=s0; red[1*256+t]=s1; red[2*256+t]=s2;
    red[3*256+t]=m00; red[4*256+t]=m01; red[5*256+t]=m02;
    red[6*256+t]=m11; red[7*256+t]=m12; red[8*256+t]=m22;
    __syncthreads();
    for (int s = 128; s > 0; s >>= 1) {
        if (t < s) {
            #pragma unroll
            for (int j = 0; j < 9; j++) red[j*256+t] += red[j*256+t+s];
        }
        __syncthreads();
    }
    if (t == 0) {
        const float invK = 1.0f / (float)K_;
        float C0 = red[0]*invK, C1 = red[256]*invK, C2 = red[512]*invK;
        g_cent[blk*3+0]=C0; g_cent[blk*3+1]=C1; g_cent[blk*3+2]=C2;
        g_S0p[blk*6+0] = red[3*256] - (float)K_*C0*C0;
        g_S0p[blk*6+1] = red[4*256] - (float)K_*C0*C1;
        g_S0p[blk*6+2] = red[5*256] - (float)K_*C0*C2;
        g_S0p[blk*6+3] = red[6*256] - (float)K_*C1*C1;
        g_S0p[blk*6+4] = red[7*256] - (float)K_*C1*C2;
        g_S0p[blk*6+5] = red[8*256] - (float)K_*C2*C2;
        int b = blk / G_, g = blk % G_;
        out[OUT_LF_OFF + (b*67+0)*15 + g] = C0;
        out[OUT_LF_OFF + (b*67+1)*15 + g] = C1;
        out[OUT_LF_OFF + (b*67+2)*15 + g] = C2;
    }
}

// layer-0 BN fold + rel3 channels of s3in
__global__ void k_bn0(const float* __restrict__ W0, const float* __restrict__ g0,
                      const float* __restrict__ b0) {
    __shared__ float S[6];
    int t = threadIdx.x, w = t >> 5, lane = t & 31;
    if (w < 6) {
        float s = 0.f;
        for (int p = lane; p < NG; p += 32) s += g_S0p[p*6 + w];
        #pragma unroll
        for (int o = 16; o > 0; o >>= 1) s += __shfl_down_sync(0xffffffffu, s, o);
        if (lane == 0) S[w] = s;
    }
    if (t < 160) {
        int bb = t / 5, sIdx = t % 5;
        float c2s[3] = {0,0,0}, c3[3] = {0,0,0};
        #pragma unroll
        for (int ss = 0; ss < 5; ss++) {
            int ga = c_split[ss*3+0], gb1 = c_split[ss*3+1], gc = c_split[ss*3+2];
            #pragma unroll
            for (int i = 0; i < 3; i++) {
                float v = (g_cent[(bb*15+ga)*3+i] + g_cent[(bb*15+gb1)*3+i]
                         + g_cent[(bb*15+gc)*3+i]) * (1.f/3.f);
                c3[i] += v;
                if (ss == sIdx) c2s[i] = v;
            }
        }
        #pragma unroll
        for (int i = 0; i < 3; i++)
            g_s3in[t*131 + i] = c2s[i] - c3[i]*0.2f;
    }
    __syncthreads();
    if (t < 64) {
        float w0 = W0[t*3+0], w1 = W0[t*3+1], w2 = W0[t*3+2];
        float var = (w0*w0*S[0] + w1*w1*S[3] + w2*w2*S[5]
                   + 2.f*(w0*w1*S[1] + w0*w2*S[2] + w1*w2*S[4])) * (1.0f/(float)NPTS);
        float scl = g0[t] * rsqrtf(var + 1e-5f);
        g_w0s[t] = make_float4(scl*w0, scl*w1, scl*w2, b0[t]);
    }
}

// ---------------- stage 1 main pass: hi-only HMMA + exact argmax refine (max-only; gamma>0) ----------------
__global__ void __launch_bounds__(256,2) k_main(const float* __restrict__ x,
                                                const float* __restrict__ W1) {
    extern __shared__ float smem[];
    uint32_t* sWhi = (uint32_t*)smem;
    uint32_t* sZ   = sWhi + 2048;
    float*    sRedV = (float*)sZ;
    int*      sRedI = (int*)(sZ + 2048);
    int*      sBI   = (int*)(sZ + 4096);
    float4*   sW0s  = (float4*)(sZ + 4608);
    float*    sCen  = (float*)(sW0s + 64);

    const int blk = blockIdx.x, t = threadIdx.x;
    const int grp = blk >> 1, half = blk & 1;
    const int lane = t & 31, w = t >> 5;
    const int wm = w >> 1, wn = w & 1;
    const int gid = lane >> 2, tig = lane & 3;

    for (int idx = t; idx < 2048; idx += 256) {
        int n = idx >> 5, kk = idx & 31;
        sWhi[idx] = h2u(__floats2half2_rn(W1[n*64 + 2*kk], W1[n*64 + 2*kk + 1]));
    }
    if (t < 64) sW0s[t] = g_w0s[t];
    if (t < 3)  sCen[t] = g_cent[grp*3 + t];
    __syncthreads();

    uint32_t bh[4][4][2];
    {
        const int n0 = wn * 32;
        #pragma unroll
        for (int nt = 0; nt < 4; nt++)
            #pragma unroll
            for (int k0 = 0; k0 < 4; k0++) {
                const int base = (n0 + nt*8 + gid)*32 + k0*8 + tig;
                bh[nt][k0][0] = sWhi[base];
                bh[nt][k0][1] = sWhi[base + 4];
            }
    }

    const float* xg = x + ((size_t)grp * K_ + half * 1024) * 3;
    const float c0 = sCen[0], c1 = sCen[1], c2v = sCen[2];
    const int h  = w >> 2;
    const int p1 = (w & 3) * 32 + lane;

    const int lrow = (lane & 7) + ((lane & 8) ? 8 : 0);
    const int lcol = (lane & 16) ? 4 : 0;
    const uint32_t zbase = smem_u32(sZ);
    const int ptb = wm * 32;
    const uint32_t a_addr0 = zbase + (uint32_t)(((ptb + lrow)*ZSTR + lcol) * 4);
    const uint32_t a_addr1 = a_addr0 + 16*ZSTR*4;

    float mx[8], sm[8], sq[8];
    int   xi[8];
    #pragma unroll
    for (int s = 0; s < 8; s++) { mx[s]=-3.402823e38f; sm[s]=0.f; sq[s]=0.f; xi[s]=0; }

    for (int tile = 0; tile < 8; tile++) {
        {
            const float* xp = xg + (size_t)(tile*128 + p1)*3;
            float r0 = xp[0]-c0, r1 = xp[1]-c1, r2 = xp[2]-c2v;
            uint32_t zh2[16];
            #pragma unroll
            for (int j = 0; j < 16; j++) {
                float4 qa = sW0s[h*32 + 2*j];
                float4 qb = sW0s[h*32 + 2*j + 1];
                float za = fmaxf(fmaf(qa.x, r0, fmaf(qa.y, r1, fmaf(qa.z, r2, qa.w))), 0.f);
                float zb = fmaxf(fmaf(qb.x, r0, fmaf(qb.y, r1, fmaf(qb.z, r2, qb.w))), 0.f);
                zh2[j] = h2u(__floats2half2_rn(za, zb));
            }
            uint4* zh = (uint4*)(sZ + p1*ZSTR + h*16);
            #pragma unroll
            for (int j4 = 0; j4 < 4; j4++)
                zh[j4] = make_uint4(zh2[j4*4], zh2[j4*4+1], zh2[j4*4+2], zh2[j4*4+3]);
        }
        __syncthreads();

        float acc[2][4][4];
        #pragma unroll
        for (int m = 0; m < 2; m++)
            #pragma unroll
            for (int nt = 0; nt < 4; nt++)
                #pragma unroll
                for (int r = 0; r < 4; r++) acc[m][nt][r] = 0.f;

        #pragma unroll
        for (int k0 = 0; k0 < 4; k0++) {
            uint32_t ah[2][4];
            LDM_X4(ah[0], a_addr0 + k0*32);
            LDM_X4(ah[1], a_addr1 + k0*32);
            #pragma unroll
            for (int m = 0; m < 2; m++)
                #pragma unroll
                for (int nt = 0; nt < 4; nt++)
                    MMA_F16(acc[m][nt], ah[m], bh[nt][k0]);
        }

        // fold stats + argmax index (max-only: all BN gammas are +1)
        #pragma unroll
        for (int m = 0; m < 2; m++)
            #pragma unroll
            for (int nt = 0; nt < 4; nt++)
                #pragma unroll
                for (int r = 0; r < 4; r++) {
                    float v = acc[m][nt][r];
                    int s = nt*2 + (r & 1);
                    int pidx = tile*128 + wm*32 + m*16 + gid + (r>>1)*8;
                    if (v > mx[s]) { mx[s] = v; xi[s] = pidx; }
                    sm[s] += v;
                    sq[s] = fmaf(v, v, sq[s]);
                }
        __syncthreads();
    }

    // cross-thread reductions (fixed-order -> deterministic): max+idx, sum, sumsq
    const int slot = wm*8 + gid;
    #pragma unroll
    for (int s = 0; s < 8; s++) {
        int ch = wn*32 + (s>>1)*8 + 2*tig + (s&1);
        sRedV[ch*32 + slot] = mx[s];
        sRedI[ch*32 + slot] = xi[s];
    }
    __syncthreads();
    if (t < 64) {
        float v = sRedV[t*32]; int bi = sRedI[t*32];
        #pragma unroll
        for (int j = 1; j < 32; j++) {
            float u = sRedV[t*32+j];
            if (u > v) { v = u; bi = sRedI[t*32+j]; }
        }
        sBI[t] = bi;
    }
    __syncthreads();
    #pragma unroll
    for (int s = 0; s < 8; s++)
        sRedV[(wn*32 + (s>>1)*8 + 2*tig + (s&1))*32 + slot] = sm[s];
    __syncthreads();
    if (t < 64) {
        float v = 0.f;
        #pragma unroll
        for (int j = 0; j < 32; j++) v += sRedV[t*32+j];
        g_psum1[t*NG2 + blk] = v;
    }
    __syncthreads();
    #pragma unroll
    for (int s = 0; s < 8; s++)
        sRedV[(wn*32 + (s>>1)*8 + 2*tig + (s&1))*32 + slot] = sq[s];
    __syncthreads();
    if (t < 64) {
        float v = 0.f;
        #pragma unroll
        for (int j = 0; j < 32; j++) v += sRedV[t*32+j];
        g_psq1[t*NG2 + blk] = v;
    }

    // epilogue: recompute EXACT fp32 y1 at argmax points only
    if (t < 64) {
        int c = t;
        int p = sBI[t];
        const float* xp = xg + (size_t)p*3;
        float r0 = xp[0]-c0, r1 = xp[1]-c1, r2 = xp[2]-c2v;
        const float4* w4 = (const float4*)(W1 + c*64);
        float y = 0.f;
        #pragma unroll 4
        for (int j = 0; j < 16; j++) {
            float4 wv = w4[j];
            float4 q0 = sW0s[4*j+0], q1 = sW0s[4*j+1], q2 = sW0s[4*j+2], q3 = sW0s[4*j+3];
            float z0 = fmaxf(fmaf(q0.x, r0, fmaf(q0.y, r1, fmaf(q0.z, r2, q0.w))), 0.f);
            float z1 = fmaxf(fmaf(q1.x, r0, fmaf(q1.y, r1, fmaf(q1.z, r2, q1.w))), 0.f);
            float z2 = fmaxf(fmaf(q2.x, r0, fmaf(q2.y, r1, fmaf(q2.z, r2, q2.w))), 0.f);
            float z3 = fmaxf(fmaf(q3.x, r0, fmaf(q3.y, r1, fmaf(q3.z, r2, q3.w))), 0.f);
            y = fmaf(wv.x, z0, y); y = fmaf(wv.y, z1, y);
            y = fmaf(wv.z, z2, y); y = fmaf(wv.w, z3, y);
        }
        g_max1[c*NG2 + blk] = y;
    }
}

// ---------------- fused layer-1 BN stats + lf1 + local_features (max path only) ----------------
__global__ void k_bn1lf1(const float* __restrict__ g1, const float* __restrict__ b1,
                         float* __restrict__ out) {
    __shared__ float rs[256], rq[256], s_sc[1], s_bi[1];
    int c = blockIdx.x, t = threadIdx.x;
    float s = 0.f, q = 0.f;
    for (int p = t; p < NG2; p += 256) { s += g_psum1[c*NG2+p]; q += g_psq1[c*NG2+p]; }
    rs[t] = s; rq[t] = q;
    __syncthreads();
    for (int o = 128; o > 0; o >>= 1) {
        if (t < o) { rs[t] += rs[t+o]; rq[t] += rq[t+o]; }
        __syncthreads();
    }
    if (t == 0) {
        float mean = rs[0] * (1.0f/(float)NPTS);
        float var  = rq[0] * (1.0f/(float)NPTS) - mean*mean;
        float scl  = g1[c] * rsqrtf(var + 1e-5f);
        s_sc[0] = scl; s_bi[0] = b1[c] - mean*scl;
    }
    __syncthreads();
    float scl = s_sc[0], bi = s_bi[0];
    for (int grp = t; grp < NG; grp += 256) {
        float v = fmaxf(g_max1[c*NG2 + 2*grp], g_max1[c*NG2 + 2*grp + 1]);
        float lf = fmaxf(fmaf(scl, v, bi), 0.f);
        g_lf1[grp*64+c] = lf;
        int b = grp / G_, g = grp % G_;
        out[OUT_LF_OFF + (b*67 + 3 + c)*15 + g] = lf;
    }
}

// layer-A BN stats: warp-per-row, lanes split the 67-dot (coalesced lf1 reads)
__global__ void k_statsA_w(const float* __restrict__ W,
                           const float* __restrict__ g, const float* __restrict__ b) {
    __shared__ float sw[67], ps[8], pq[8];
    int c = blockIdx.x, t = threadIdx.x;
    int wp = t >> 5, l = t & 31;
    if (t < 67) sw[t] = W[c*67+t];
    __syncthreads();
    float s = 0.f, q = 0.f;
    for (int row = wp; row < 480; row += 8) {
        int bb = row / 15, r = row % 15, sIdx = r / 3, m = r % 3;
        int gg = c_split[sIdx*3+m];
        const float* lf = g_lf1 + (bb*15+gg)*64;
        float v;
        if (l < 3) {
            int ga = c_split[sIdx*3+0], gb1 = c_split[sIdx*3+1], gc = c_split[sIdx*3+2];
            float c2 = (g_cent[(bb*15+ga)*3+l] + g_cent[(bb*15+gb1)*3+l]
                      + g_cent[(bb*15+gc)*3+l]) * (1.f/3.f);
            float f0 = g_cent[(bb*15+gg)*3+l] - c2;
            v = f0*sw[l] + lf[l+29]*sw[l+32] + lf[l+61]*sw[l+64];
        } else {
            v = lf[l-3]*sw[l] + lf[l+29]*sw[l+32];
        }
        #pragma unroll
        for (int o = 16; o > 0; o >>= 1) v += __shfl_down_sync(0xffffffffu, v, o);
        if (l == 0) { s += v; q = fmaf(v, v, q); }
    }
    if (l == 0) { ps[wp] = s; pq[wp] = q; }
    __syncthreads();
    if (t == 0) {
        float ss = 0.f, qq = 0.f;
        #pragma unroll
        for (int j = 0; j < 8; j++) { ss += ps[j]; qq += pq[j]; }
        float mean = ss * (1.f/480.f);
        float var  = qq * (1.f/480.f) - mean*mean;
        float scl  = g[c] * rsqrtf(var + 1e-5f);
        g_scaleA[c] = scl;
        g_biasA[c]  = b[c] - mean*scl;
    }
}

// fused gemmA + BN-relu + gemmB; transposed weights -> coalesced
__global__ void k_gemmAB() {
    __shared__ float f[67], z[128];
    int p = blockIdx.x, c = threadIdx.x;
    int bb = p / 15, r = p % 15, sIdx = r / 3, m = r % 3;
    int gg = c_split[sIdx*3+m];
    if (c < 3) {
        int ga = c_split[sIdx*3+0], gb1 = c_split[sIdx*3+1], gc = c_split[sIdx*3+2];
        float c2 = (g_cent[(bb*15+ga)*3+c] + g_cent[(bb*15+gb1)*3+c]
                  + g_cent[(bb*15+gc)*3+c]) * (1.f/3.f);
        f[c] = g_cent[(bb*15+gg)*3+c] - c2;
    }
    if (c < 64) f[3+c] = g_lf1[(bb*15+gg)*64+c];
    __syncthreads();
    float yA = 0.f;
    #pragma unroll
    for (int i = 0; i < 67; i++) yA = fmaf(g_WAT[i*128+c], f[i], yA);
    z[c] = fmaxf(fmaf(g_scaleA[c], yA, g_biasA[c]), 0.f);
    __syncthreads();
    float yB = 0.f;
    #pragma unroll
    for (int i = 0; i < 128; i++) yB = fmaf(g_WBT[i*128+c], z[i], yB);
    g_yB[p*128+c] = yB;
}

// fused statsB + s3in assembly (max path only)
__global__ void k_statsB_s3in(const float* __restrict__ g, const float* __restrict__ b) {
    __shared__ float rs[256], rq[256], s_sc[1], s_bi[1];
    int c = blockIdx.x, t = threadIdx.x;
    float s = 0.f, q = 0.f;
    for (int p = t; p < 480; p += 256) { float v = g_yB[p*128+c]; s += v; q = fmaf(v,v,q); }
    rs[t] = s; rq[t] = q;
    __syncthreads();
    for (int o = 128; o > 0; o >>= 1) {
        if (t < o) { rs[t] += rs[t+o]; rq[t] += rq[t+o]; }
        __syncthreads();
    }
    if (t == 0) {
        float mean = rs[0] * (1.f/480.f);
        float var  = rq[0] * (1.f/480.f) - mean*mean;
        float scl  = g[c] * rsqrtf(var + 1e-5f);
        s_sc[0] = scl; s_bi[0] = b[c] - mean*scl;
    }
    __syncthreads();
    float scl = s_sc[0], bi = s_bi[0];
    for (int bs = t; bs < 160; bs += 256) {
        float v0 = g_yB[(bs*3+0)*128+c];
        float v1 = g_yB[(bs*3+1)*128+c];
        float v2 = g_yB[(bs*3+2)*128+c];
        float v  = fmaxf(v0, fmaxf(v1, v2));
        g_s3in[bs*131 + 3 + c] = fmaxf(fmaf(scl, v, bi), 0.f);
    }
}

// layer-C BN stats: warp-per-row, lanes split the 131-dot
__global__ void k_statsC_w(const float* __restrict__ W,
                           const float* __restrict__ g, const float* __restrict__ b) {
    __shared__ float sw[131], ps[8], pq[8];
    int c = blockIdx.x, t = threadIdx.x;
    int wp = t >> 5, l = t & 31;
    if (t < 131) sw[t] = W[c*131+t];
    __syncthreads();
    float s = 0.f, q = 0.f;
    for (int row = wp; row < 160; row += 8) {
        const float* f = g_s3in + row*131;
        float v = f[l]*sw[l] + f[l+32]*sw[l+32] + f[l+64]*sw[l+64] + f[l+96]*sw[l+96];
        if (l < 3) v = fmaf(f[l+128], sw[l+128], v);
        #pragma unroll
        for (int o = 16; o > 0; o >>= 1) v += __shfl_down_sync(0xffffffffu, v, o);
        if (l == 0) { s += v; q = fmaf(v, v, q); }
    }
    if (l == 0) { ps[wp] = s; pq[wp] = q; }
    __syncthreads();
    if (t == 0) {
        float ss = 0.f, qq = 0.f;
        #pragma unroll
        for (int j = 0; j < 8; j++) { ss += ps[j]; qq += pq[j]; }
        float mean = ss * (1.f/160.f);
        float var  = qq * (1.f/160.f) - mean*mean;
        float scl  = g[c] * rsqrtf(var + 1e-5f);
        g_scaleC[c] = scl;
        g_biasC[c]  = b[c] - mean*scl;
    }
}

// fused gemmC + BN-relu + gemmD; transposed weights -> coalesced
__global__ void k_gemmCD() {
    __shared__ float f[131], z[256];
    int bs = blockIdx.x, c = threadIdx.x;
    if (c < 131) f[c] = g_s3in[bs*131+c];
    __syncthreads();
    float yC = 0.f;
    #pragma unroll
    for (int i = 0; i < 131; i++) yC = fmaf(g_WCT[i*256+c], f[i], yC);
    z[c] = fmaxf(fmaf(g_scaleC[c], yC, g_biasC[c]), 0.f);
    __syncthreads();
    float yD = 0.f;
    #pragma unroll
    for (int i = 0; i < 256; i++) yD = fmaf(g_WDT[i*256+c], z[i], yD);
    g_yD[bs*256+c] = yD;
}

// fused statsD + final output (max path only)
__global__ void k_statsD_out(const float* __restrict__ g, const float* __restrict__ b,
                             float* __restrict__ out) {
    __shared__ float rs[256], rq[256], s_sc[1], s_bi[1];
    int c = blockIdx.x, t = threadIdx.x;
    float s = 0.f, q = 0.f;
    if (t < 160) { float v = g_yD[t*256+c]; s = v; q = v*v; }
    rs[t] = s; rq[t] = q;
    __syncthreads();
    for (int o = 128; o > 0; o >>= 1) {
        if (t < o) { rs[t] += rs[t+o]; rq[t] += rq[t+o]; }
        __syncthreads();
    }
    if (t == 0) {
        float mean = rs[0] * (1.f/160.f);
        float var  = rq[0] * (1.f/160.f) - mean*mean;
        float scl  = g[c] * rsqrtf(var + 1e-5f);
        s_sc[0] = scl; s_bi[0] = b[c] - mean*scl;
    }
    __syncthreads();
    float scl = s_sc[0], bi = s_bi[0];
    if (t < 32) {
        float v = -3.402823e38f;
        #pragma unroll
        for (int ss = 0; ss < 5; ss++)
            v = fmaxf(v, g_yD[(t*5+ss)*256+c]);
        out[t*256+c] = fmaxf(fmaf(scl, v, bi), 0.f);
    }
}

// ---------------- launch ----------------
extern "C" void kernel_launch(void* const* d_in, const int* in_sizes, int n_in,
                              void* d_out, int out_size) {
    const float* x      = (const float*)d_in[0];
    const float* la0_w0 = (const float*)d_in[1];
    const float* la0_g0 = (const float*)d_in[2];
    const float* la0_b0 = (const float*)d_in[3];
    const float* la0_w1 = (const float*)d_in[4];
    const float* la0_g1 = (const float*)d_in[5];
    const float* la0_b1 = (const float*)d_in[6];
    const float* la1_w0 = (const float*)d_in[7];
    const float* la1_g0 = (const float*)d_in[8];
    const float* la1_b0 = (const float*)d_in[9];
    const float* la1_w1 = (const float*)d_in[10];
    const float* la1_g1 = (const float*)d_in[11];
    const float* la1_b1 = (const float*)d_in[12];
    const float* la2_w0 = (const float*)d_in[13];
    const float* la2_g0 = (const float*)d_in[14];
    const float* la2_b0 = (const float*)d_in[15];
    const float* la2_w1 = (const float*)d_in[16];
    const float* la2_g1 = (const float*)d_in[17];
    const float* la2_b1 = (const float*)d_in[18];
    float* out = (float*)d_out;

    const int SMEM_MAIN = (2048 + 4608 + 256 + 4) * 4;
    cudaFuncSetAttribute(k_main, cudaFuncAttributeMaxDynamicSharedMemorySize, SMEM_MAIN);

    k_centroid<<<NG + NT, 256>>>(x, out, la1_w0, la1_w1, la2_w0, la2_w1);
    k_bn0<<<1, 192>>>(la0_w0, la0_g0, la0_b0);
    k_main<<<NG2, 256, SMEM_MAIN>>>(x, la0_w1);
    k_bn1lf1<<<64, 256>>>(la0_g1, la0_b1, out);
    k_statsA_w<<<128, 256>>>(la1_w0, la1_g0, la1_b0);
    k_gemmAB<<<480, 128>>>();
    k_statsB_s3in<<<128, 256>>>(la1_g1, la1_b1);
    k_statsC_w<<<256, 256>>>(la2_w0, la2_g0, la2_b0);
    k_gemmCD<<<160, 256>>>();
    k_statsD_out<<<256, 256>>>(la2_g1, la2_b1, out);
}